// round 1
// baseline (speedup 1.0000x reference)
#include <cuda_runtime.h>
#include <math.h>

#define T_TOK   2048
#define H_DIM   128
#define H4_DIM  512
#define N_NODES 256
#define TB      16   // token chunk per pass

// Scratch (allocation-free per harness rules)
__device__ int g_count[N_NODES];
__device__ int g_tokens[N_NODES * T_TOK];

__global__ void zero_counts_kernel() {
    g_count[threadIdx.x] = 0;
}

__global__ void build_lists_kernel(const int* __restrict__ node_ind) {
    int t = blockIdx.x * blockDim.x + threadIdx.x;
    if (t < T_TOK) {
        int n = node_ind[t];
        int pos = atomicAdd(&g_count[n], 1);
        g_tokens[n * T_TOK + pos] = t;
    }
}

__global__ __launch_bounds__(512, 2)
void mlp_nodes_kernel(const float* __restrict__ x,
                      const float* __restrict__ W1,
                      const float* __restrict__ b1,
                      const float* __restrict__ W2,
                      const float* __restrict__ b2,
                      float* __restrict__ out) {
    __shared__ float xs[TB][H_DIM];    // 8 KB
    __shared__ float hs[TB][H4_DIM];   // 32 KB
    __shared__ int   stoks[TB];

    const int n = blockIdx.x;
    const int nt_total = g_count[n];
    if (nt_total == 0) return;

    const int tid  = threadIdx.x;
    const int w    = tid >> 5;   // warp 0..15
    const int lane = tid & 31;

    const float* W1n = W1 + (size_t)n * H4_DIM * H_DIM;
    const float* W2n = W2 + (size_t)n * H_DIM * H4_DIM;
    const float* b1n = b1 + n * H4_DIM;
    const float* b2n = b2 + n * H_DIM;

    for (int base = 0; base < nt_total; base += TB) {
        const int nt = min(TB, nt_total - base);

        // Stage token ids + x rows for this chunk
        if (tid < nt) stoks[tid] = g_tokens[n * T_TOK + base + tid];
        __syncthreads();
        if (tid < nt * 32) {
            int tk = tid >> 5;
            int l4 = tid & 31;
            float4 v = ((const float4*)(x + (size_t)stoks[tk] * H_DIM))[l4];
            ((float4*)xs[tk])[l4] = v;
        }
        __syncthreads();

        // ---- Layer 1: h[t][o] = gelu(W1n[o,:] . x[t] + b1n[o]) ----
        // warp w owns rows o = w, w+16, ... (32 rows each). One float4 of the
        // weight row per lane (coalesced 512B/warp), reused across all tokens.
        for (int o = w; o < H4_DIM; o += 16) {
            const float4 wv = ((const float4*)(W1n + (size_t)o * H_DIM))[lane];
            float acc[TB];
            #pragma unroll
            for (int t = 0; t < TB; t++) {
                acc[t] = 0.f;
                if (t < nt) {
                    float4 xv = ((const float4*)xs[t])[lane];
                    acc[t] = wv.x * xv.x + wv.y * xv.y + wv.z * xv.z + wv.w * xv.w;
                }
            }
            #pragma unroll
            for (int t = 0; t < TB; t++) {
                if (t < nt) {
                    float v = acc[t];
                    #pragma unroll
                    for (int s = 16; s > 0; s >>= 1)
                        v += __shfl_xor_sync(0xffffffffu, v, s);
                    if (lane == 0) {
                        v += b1n[o];
                        // exact (erf) GELU
                        hs[t][o] = 0.5f * v * (1.0f + erff(v * 0.70710678118654752f));
                    }
                }
            }
        }
        __syncthreads();

        // ---- Layer 2: out[t][o] = W2n[o,:] . h[t] + b2n[o] ----
        for (int o = w; o < H_DIM; o += 16) {
            const float* wrow = W2n + (size_t)o * H4_DIM;
            float acc[TB];
            #pragma unroll
            for (int t = 0; t < TB; t++) acc[t] = 0.f;
            #pragma unroll
            for (int kc = 0; kc < 4; kc++) {
                const float4 wv = ((const float4*)(wrow + kc * H_DIM))[lane];
                #pragma unroll
                for (int t = 0; t < TB; t++) {
                    if (t < nt) {
                        float4 hv = ((const float4*)(hs[t] + kc * H_DIM))[lane];
                        acc[t] += wv.x * hv.x + wv.y * hv.y + wv.z * hv.z + wv.w * hv.w;
                    }
                }
            }
            #pragma unroll
            for (int t = 0; t < TB; t++) {
                if (t < nt) {
                    float v = acc[t];
                    #pragma unroll
                    for (int s = 16; s > 0; s >>= 1)
                        v += __shfl_xor_sync(0xffffffffu, v, s);
                    if (lane == 0)
                        out[(size_t)stoks[t] * H_DIM + o] = v + b2n[o];
                }
            }
        }
        __syncthreads();
    }
}

extern "C" void kernel_launch(void* const* d_in, const int* in_sizes, int n_in,
                              void* d_out, int out_size) {
    const float* x        = (const float*)d_in[0];
    const int*   node_ind = (const int*)  d_in[1];
    const float* W1       = (const float*)d_in[2];
    const float* b1       = (const float*)d_in[3];
    const float* W2       = (const float*)d_in[4];
    const float* b2       = (const float*)d_in[5];
    float*       out      = (float*)d_out;

    zero_counts_kernel<<<1, N_NODES>>>();
    build_lists_kernel<<<(T_TOK + 255) / 256, 256>>>(node_ind);
    mlp_nodes_kernel<<<N_NODES, 512>>>(x, W1, b1, W2, b2, out);
}

// round 4
// speedup vs baseline: 2.4985x; 2.4985x over previous
#include <cuda_runtime.h>
#include <math.h>

#define T_TOK   2048
#define H_DIM   128
#define H4_DIM  512
#define N_NODES 256
#define TB      8    // token chunk per pass (Poisson mean = 8 tokens/node)

// Scratch (allocation-free per harness rules)
__device__ int g_count[N_NODES];
__device__ int g_tokens[N_NODES * T_TOK];

__global__ void zero_counts_kernel() {
    g_count[threadIdx.x] = 0;
}

__global__ void build_lists_kernel(const int* __restrict__ node_ind) {
    int t = blockIdx.x * blockDim.x + threadIdx.x;
    if (t < T_TOK) {
        int n = node_ind[t];
        int pos = atomicAdd(&g_count[n], 1);
        g_tokens[n * T_TOK + pos] = t;
    }
}

__device__ __forceinline__ float gelu_exact(float v) {
    return 0.5f * v * (1.0f + erff(v * 0.70710678118654752f));
}

// Warp layout: 16 warps. Each warp handles 4 rows at a time; each row's dot
// product is split across 8 lanes (16 floats per lane, owned as 4 float4s at
// stride-8 positions j*8+c so smem reads are conflict-free / broadcast).
// Reduction is 3 shfl_xor steps within the 8-lane group; 4 rows reduce in
// parallel across the 4 lane groups.
__global__ __launch_bounds__(512, 2)
void mlp_nodes_kernel(const float* __restrict__ x,
                      const float* __restrict__ W1,
                      const float* __restrict__ b1,
                      const float* __restrict__ W2,
                      const float* __restrict__ b2,
                      float* __restrict__ out) {
    __shared__ float xs[TB][H_DIM];    // 4 KB
    __shared__ float hs[TB][H4_DIM];   // 16 KB
    __shared__ int   stoks[TB];

    const int n = blockIdx.x;
    const int nt_total = g_count[n];
    if (nt_total == 0) return;

    const int tid  = threadIdx.x;
    const int w    = tid >> 5;    // warp 0..15
    const int lane = tid & 31;
    const int g    = lane >> 3;   // row group 0..3
    const int c    = lane & 7;    // chunk within row 0..7

    const float* W1n = W1 + (size_t)n * H4_DIM * H_DIM;
    const float* W2n = W2 + (size_t)n * H_DIM * H4_DIM;
    const float* b1n = b1 + n * H4_DIM;
    const float* b2n = b2 + n * H_DIM;

    for (int base = 0; base < nt_total; base += TB) {
        const int nt = min(TB, nt_total - base);

        // Stage token ids + x rows for this chunk
        if (tid < nt) stoks[tid] = g_tokens[n * T_TOK + base + tid];
        __syncthreads();
        if (tid < nt * 32) {
            int tk = tid >> 5;
            int l4 = tid & 31;
            ((float4*)xs[tk])[l4] =
                ((const float4*)(x + (size_t)stoks[tk] * H_DIM))[l4];
        }
        __syncthreads();

        // ---- Layer 1: h[t][r] = gelu(W1n[r,:] . x[t] + b1n[r]) ----
        #pragma unroll
        for (int it = 0; it < 8; it++) {
            const int r = it * 64 + w * 4 + g;
            const float4* wr = (const float4*)(W1n + (size_t)r * H_DIM);
            float4 wv[4];
            #pragma unroll
            for (int j = 0; j < 4; j++) wv[j] = wr[j * 8 + c];

            float acc[TB];
            #pragma unroll
            for (int t = 0; t < TB; t++) {
                acc[t] = 0.f;
                if (t < nt) {
                    #pragma unroll
                    for (int j = 0; j < 4; j++) {
                        float4 xv = ((const float4*)xs[t])[j * 8 + c];
                        acc[t] += wv[j].x * xv.x + wv[j].y * xv.y
                                + wv[j].z * xv.z + wv[j].w * xv.w;
                    }
                }
            }
            #pragma unroll
            for (int t = 0; t < TB; t++) {
                if (t < nt) {
                    float v = acc[t];
                    v += __shfl_xor_sync(0xffffffffu, v, 4);
                    v += __shfl_xor_sync(0xffffffffu, v, 2);
                    v += __shfl_xor_sync(0xffffffffu, v, 1);
                    if (c == 0) hs[t][r] = gelu_exact(v + b1n[r]);
                }
            }
        }
        __syncthreads();

        // ---- Layer 2: out[t][r] = W2n[r,:] . h[t] + b2n[r] ----
        #pragma unroll
        for (int it = 0; it < 2; it++) {
            const int r = it * 64 + w * 4 + g;
            const float* wrow = W2n + (size_t)r * H4_DIM;
            float acc[TB];
            #pragma unroll
            for (int t = 0; t < TB; t++) acc[t] = 0.f;

            #pragma unroll
            for (int kc = 0; kc < 4; kc++) {
                const float4* wr = (const float4*)(wrow + kc * H_DIM);
                float4 wv[4];
                #pragma unroll
                for (int j = 0; j < 4; j++) wv[j] = wr[j * 8 + c];
                #pragma unroll
                for (int t = 0; t < TB; t++) {
                    if (t < nt) {
                        #pragma unroll
                        for (int j = 0; j < 4; j++) {
                            float4 hv = ((const float4*)(hs[t] + kc * H_DIM))[j * 8 + c];
                            acc[t] += wv[j].x * hv.x + wv[j].y * hv.y
                                    + wv[j].z * hv.z + wv[j].w * hv.w;
                        }
                    }
                }
            }
            #pragma unroll
            for (int t = 0; t < TB; t++) {
                if (t < nt) {
                    float v = acc[t];
                    v += __shfl_xor_sync(0xffffffffu, v, 4);
                    v += __shfl_xor_sync(0xffffffffu, v, 2);
                    v += __shfl_xor_sync(0xffffffffu, v, 1);
                    if (c == 0)
                        out[(size_t)stoks[t] * H_DIM + r] = v + b2n[r];
                }
            }
        }
        __syncthreads();
    }
}

extern "C" void kernel_launch(void* const* d_in, const int* in_sizes, int n_in,
                              void* d_out, int out_size) {
    const float* x        = (const float*)d_in[0];
    const int*   node_ind = (const int*)  d_in[1];
    const float* W1       = (const float*)d_in[2];
    const float* b1       = (const float*)d_in[3];
    const float* W2       = (const float*)d_in[4];
    const float* b2       = (const float*)d_in[5];
    float*       out      = (float*)d_out;

    zero_counts_kernel<<<1, N_NODES>>>();
    build_lists_kernel<<<(T_TOK + 255) / 256, 256>>>(node_ind);
    mlp_nodes_kernel<<<N_NODES, 512>>>(x, W1, b1, W2, b2, out);
}

// round 5
// speedup vs baseline: 2.6355x; 1.0548x over previous
#include <cuda_runtime.h>
#include <math.h>

#define T_TOK   2048
#define H_DIM   128
#define H4_DIM  512
#define N_NODES 256
#define TB      8    // token chunk per pass

// Scratch (allocation-free per harness rules)
__device__ int   g_count[N_NODES];
__device__ int   g_tokens[N_NODES * T_TOK];
__device__ float g_h[T_TOK * H4_DIM];   // 4 MB intermediate (L2-resident)

// Single-block prep: zero counts + build per-node token lists via smem atomics.
__global__ void prep_kernel(const int* __restrict__ node_ind) {
    __shared__ int scnt[N_NODES];
    int tid = threadIdx.x;
    scnt[tid] = 0;
    __syncthreads();
    for (int t = tid; t < T_TOK; t += N_NODES) {
        int n = node_ind[t];
        int pos = atomicAdd(&scnt[n], 1);
        g_tokens[n * T_TOK + pos] = t;
    }
    __syncthreads();
    g_count[tid] = scnt[tid];
}

__device__ __forceinline__ float gelu_exact(float v) {
    return 0.5f * v * (1.0f + erff(v * 0.70710678118654752f));
}

// ---- Layer 1: grid = N_NODES*4 CTAs. CTA (n,q) owns rows [q*128,(q+1)*128)
// of W1[n] (64 KB), loaded into registers ONCE, reused over all tokens of n.
// Warp w handles rows it*64 + w*4 + g (it=0,1); row dot split over 8 lanes.
__global__ __launch_bounds__(512, 2)
void layer1_kernel(const float* __restrict__ x,
                   const float* __restrict__ W1,
                   const float* __restrict__ b1) {
    __shared__ float xs[TB][H_DIM];
    __shared__ int   stoks[TB];

    const int b = blockIdx.x;
    const int n = b >> 2;
    const int q = b & 3;
    const int nt_total = g_count[n];
    if (nt_total == 0) return;

    const int tid  = threadIdx.x;
    const int w    = tid >> 5;
    const int lane = tid & 31;
    const int g    = lane >> 3;   // row group 0..3
    const int c    = lane & 7;    // chunk 0..7 (16 floats per lane per row)

    const float* W1c = W1 + (size_t)n * H4_DIM * H_DIM + (size_t)q * 128 * H_DIM;
    const float* b1c = b1 + n * H4_DIM + q * 128;

    // Load weights once: 2 row-sets x 4 float4 = 32 regs
    float4 wv[2][4];
    #pragma unroll
    for (int it = 0; it < 2; it++) {
        const int rr = it * 64 + w * 4 + g;
        const float4* wr = (const float4*)(W1c + (size_t)rr * H_DIM);
        #pragma unroll
        for (int j = 0; j < 4; j++) wv[it][j] = wr[j * 8 + c];
    }

    for (int base = 0; base < nt_total; base += TB) {
        const int nt = min(TB, nt_total - base);

        __syncthreads();
        if (tid < nt) stoks[tid] = g_tokens[n * T_TOK + base + tid];
        __syncthreads();
        if (tid < nt * 32) {
            int tk = tid >> 5;
            int l4 = tid & 31;
            ((float4*)xs[tk])[l4] =
                ((const float4*)(x + (size_t)stoks[tk] * H_DIM))[l4];
        }
        __syncthreads();

        #pragma unroll
        for (int it = 0; it < 2; it++) {
            const int rr = it * 64 + w * 4 + g;
            float acc[TB];
            #pragma unroll
            for (int t = 0; t < TB; t++) {
                acc[t] = 0.f;
                if (t < nt) {
                    #pragma unroll
                    for (int j = 0; j < 4; j++) {
                        float4 xv = ((const float4*)xs[t])[j * 8 + c];
                        acc[t] += wv[it][j].x * xv.x + wv[it][j].y * xv.y
                                + wv[it][j].z * xv.z + wv[it][j].w * xv.w;
                    }
                }
            }
            #pragma unroll
            for (int t = 0; t < TB; t++) {
                if (t < nt) {
                    float v = acc[t];
                    v += __shfl_xor_sync(0xffffffffu, v, 4);
                    v += __shfl_xor_sync(0xffffffffu, v, 2);
                    v += __shfl_xor_sync(0xffffffffu, v, 1);
                    if (c == 0)
                        g_h[(size_t)stoks[t] * H4_DIM + q * 128 + rr] =
                            gelu_exact(v + b1c[rr]);
                }
            }
        }
    }
}

// ---- Layer 2: grid = N_NODES*4 CTAs. CTA (n,q) owns rows [q*32,(q+1)*32)
// of W2[n] (32 rows x 512 = 64 KB), in registers once. Warp w handles rows
// w + it*16 (it=0,1); row dot split over 32 lanes (4 float4/lane).
__global__ __launch_bounds__(512, 2)
void layer2_kernel(const float* __restrict__ W2,
                   const float* __restrict__ b2,
                   float* __restrict__ out) {
    __shared__ float hs[TB][H4_DIM];   // 16 KB
    __shared__ int   stoks[TB];

    const int b = blockIdx.x;
    const int n = b >> 2;
    const int q = b & 3;
    const int nt_total = g_count[n];
    if (nt_total == 0) return;

    const int tid  = threadIdx.x;
    const int w    = tid >> 5;
    const int lane = tid & 31;

    const float* W2c = W2 + (size_t)n * H_DIM * H4_DIM + (size_t)q * 32 * H4_DIM;
    const float* b2c = b2 + n * H_DIM + q * 32;

    // Load weights once: 2 rows x 4 float4 = 32 regs
    float4 wv[2][4];
    #pragma unroll
    for (int it = 0; it < 2; it++) {
        const int rr = w + it * 16;
        const float4* wr = (const float4*)(W2c + (size_t)rr * H4_DIM);
        #pragma unroll
        for (int j = 0; j < 4; j++) wv[it][j] = wr[j * 32 + lane];
    }

    for (int base = 0; base < nt_total; base += TB) {
        const int nt = min(TB, nt_total - base);

        __syncthreads();
        if (tid < nt) stoks[tid] = g_tokens[n * T_TOK + base + tid];
        __syncthreads();
        // Stage h rows: nt*128 float4; 512 threads -> up to 2 each
        #pragma unroll
        for (int k = 0; k < 2; k++) {
            int idx = tid + k * 512;
            int tk = idx >> 7;        // token 0..7
            int l4 = idx & 127;       // float4 within row
            if (tk < nt)
                ((float4*)hs[tk])[l4] =
                    ((const float4*)(g_h + (size_t)stoks[tk] * H4_DIM))[l4];
        }
        __syncthreads();

        #pragma unroll
        for (int it = 0; it < 2; it++) {
            const int rr = w + it * 16;
            float acc[TB];
            #pragma unroll
            for (int t = 0; t < TB; t++) {
                acc[t] = 0.f;
                if (t < nt) {
                    #pragma unroll
                    for (int j = 0; j < 4; j++) {
                        float4 hv = ((const float4*)hs[t])[j * 32 + lane];
                        acc[t] += wv[it][j].x * hv.x + wv[it][j].y * hv.y
                                + wv[it][j].z * hv.z + wv[it][j].w * hv.w;
                    }
                }
            }
            #pragma unroll
            for (int t = 0; t < TB; t++) {
                if (t < nt) {
                    float v = acc[t];
                    #pragma unroll
                    for (int s = 16; s > 0; s >>= 1)
                        v += __shfl_xor_sync(0xffffffffu, v, s);
                    if (lane == 0)
                        out[(size_t)stoks[t] * H_DIM + q * 32 + rr] = v + b2c[rr];
                }
            }
        }
    }
}

extern "C" void kernel_launch(void* const* d_in, const int* in_sizes, int n_in,
                              void* d_out, int out_size) {
    const float* x        = (const float*)d_in[0];
    const int*   node_ind = (const int*)  d_in[1];
    const float* W1       = (const float*)d_in[2];
    const float* b1       = (const float*)d_in[3];
    const float* W2       = (const float*)d_in[4];
    const float* b2       = (const float*)d_in[5];
    float*       out      = (float*)d_out;

    prep_kernel<<<1, N_NODES>>>(node_ind);
    layer1_kernel<<<N_NODES * 4, 512>>>(x, W1, b1);
    layer2_kernel<<<N_NODES * 4, 512>>>(W2, b2, out);
}